// round 8
// baseline (speedup 1.0000x reference)
#include <cuda_runtime.h>
#include <cuda_bf16.h>
#include <math.h>
#include <stdint.h>

// Problem constants
#define BB 4
#define SS 4096
#define DD 2048
#define NH 16
#define HH 128
#define MTOT (BB * SS)   // 16384

// Chunked pipeline
#define NCH 8
#define CH  (SS / NCH)   // 512

typedef unsigned long long ull;

// ---- packed fp32x2 helpers ----
__device__ __forceinline__ ull ffma2(ull a, ull b, ull c) {
    ull d;
    asm("fma.rn.f32x2 %0, %1, %2, %3;" : "=l"(d) : "l"(a), "l"(b), "l"(c));
    return d;
}
__device__ __forceinline__ ull addf2(ull a, ull b) {
    ull d;
    asm("add.rn.f32x2 %0, %1, %2;" : "=l"(d) : "l"(a), "l"(b));
    return d;
}
__device__ __forceinline__ ull pack2(float lo, float hi) {
    ull r;
    asm("mov.b64 %0, {%1, %2};" : "=l"(r) : "f"(lo), "f"(hi));
    return r;
}
__device__ __forceinline__ void unpack2(ull v, float& lo, float& hi) {
    asm("mov.b64 {%0, %1}, %2;" : "=f"(lo), "=f"(hi) : "l"(v));
}
__device__ __forceinline__ uint32_t smem_u32(const void* p) {
    uint32_t a;
    asm("{ .reg .u64 t; cvta.to.shared.u64 t, %1; cvt.u32.u64 %0, t; }" : "=r"(a) : "l"(p));
    return a;
}

// fast tanh: (e^{2x}-1)/(e^{2x}+1) via MUFU ex2/rcp; rel err ~1e-7
__device__ __forceinline__ float fast_tanh(float x) {
    float t = fminf(x * 2.885390081777927f, 80.0f);
    float e;
    asm("ex2.approx.f32 %0, %1;" : "=f"(e) : "f"(t));
    float r;
    asm("rcp.approx.f32 %0, %1;" : "=f"(r) : "f"(e + 1.0f));
    return (e - 1.0f) * r;
}

// ---- mma.sync / ldmatrix / cp.async (plain PTX, assembles at compute_103) ----
__device__ __forceinline__ void ldsm4(uint32_t* r, uint32_t addr) {
    asm volatile("ldmatrix.sync.aligned.m8n8.x4.shared.b16 {%0,%1,%2,%3}, [%4];"
                 : "=r"(r[0]), "=r"(r[1]), "=r"(r[2]), "=r"(r[3]) : "r"(addr));
}
__device__ __forceinline__ void ldsm4t(uint32_t* r, uint32_t addr) {
    asm volatile("ldmatrix.sync.aligned.m8n8.x4.trans.shared.b16 {%0,%1,%2,%3}, [%4];"
                 : "=r"(r[0]), "=r"(r[1]), "=r"(r[2]), "=r"(r[3]) : "r"(addr));
}
__device__ __forceinline__ void mma_bf16(float* c, const uint32_t* a, uint32_t b0, uint32_t b1) {
    asm volatile("mma.sync.aligned.m16n8k16.row.col.f32.bf16.bf16.f32 "
                 "{%0,%1,%2,%3}, {%4,%5,%6,%7}, {%8,%9}, {%0,%1,%2,%3};"
                 : "+f"(c[0]), "+f"(c[1]), "+f"(c[2]), "+f"(c[3])
                 : "r"(a[0]), "r"(a[1]), "r"(a[2]), "r"(a[3]), "r"(b0), "r"(b1));
}
__device__ __forceinline__ void cp_async16(uint32_t saddr, const void* gaddr) {
    asm volatile("cp.async.cg.shared.global [%0], [%1], 16;"
                 :: "r"(saddr), "l"(gaddr) : "memory");
}

// ---- scratch (device globals; no allocation allowed) ----
__device__ float g_x[33554432];                         // (B,S,D) post-input-projection fp32
__device__ __nv_bfloat16 g_inhi[33554432], g_inlo[33554432];  // input split
__device__ __nv_bfloat16 g_yhi[33554432],  g_ylo[33554432];   // scan output split
__device__ __nv_bfloat16 g_wihi[4194304],  g_wilo[4194304];   // w_in split
__device__ __nv_bfloat16 g_wohi[4194304],  g_wolo[4194304];   // w_out split
__device__ float g_state[BB * NH * HH];

// ============================================================================
// fp32 -> bf16 hi/lo split (elementwise, float4 per thread)
// ============================================================================
__global__ __launch_bounds__(256)
void cvt_split_kernel(const float* __restrict__ src,
                      __nv_bfloat16* __restrict__ hi,
                      __nv_bfloat16* __restrict__ lo, int n4) {
    int i = blockIdx.x * 256 + threadIdx.x;
    if (i >= n4) return;
    float4 v = ((const float4*)src)[i];
    float f[4] = {v.x, v.y, v.z, v.w};
    uint32_t hw[4], lw[4];
    #pragma unroll
    for (int j = 0; j < 4; j++) {
        __nv_bfloat16 h = __float2bfloat16(f[j]);
        float r = f[j] - __bfloat162float(h);
        __nv_bfloat16 l = __float2bfloat16(r);
        hw[j] = *(unsigned short*)&h;
        lw[j] = *(unsigned short*)&l;
    }
    *(uint2*)(hi + 4 * (size_t)i) = make_uint2(hw[0] | (hw[1] << 16), hw[2] | (hw[3] << 16));
    *(uint2*)(lo + 4 * (size_t)i) = make_uint2(lw[0] | (lw[1] << 16), lw[2] | (lw[3] << 16));
}

// ============================================================================
// bf16 3-product-split GEMM, pre-converted operands, cp.async 3-stage pipeline.
// Tile 128x128, BK=32, 256 threads = 8 warps (4M x 2N), 2 CTAs/SM.
// Stage layout (32KB): Ahi@0, Alo@8K, Bhi@16K, Blo@24K.
// ============================================================================
#define AHI 0
#define ALO 8192
#define BHI 16384
#define BLO 24576
#define STAGE 32768

__device__ __forceinline__ uint32_t aoff(int r, int c) {
    return (uint32_t)(r * 64 + ((c ^ ((r >> 1) & 3)) * 16));
}
__device__ __forceinline__ uint32_t boff(int kr, int c) {
    return (uint32_t)(kr * 256 + ((c ^ (kr & 7)) * 16));
}

__global__ __launch_bounds__(256, 2)
void gemm_mma_kernel(const __nv_bfloat16* __restrict__ Ahi, const __nv_bfloat16* __restrict__ Alo,
                     const __nv_bfloat16* __restrict__ Bhi, const __nv_bfloat16* __restrict__ Blo,
                     const float* __restrict__ bias, float* __restrict__ C, int s_base) {
    extern __shared__ __align__(128) char smem[];
    const uint32_t sb = smem_u32(smem);

    const int t    = threadIdx.x;
    const int lane = t & 31;
    const int wid  = t >> 5;
    const int wm   = wid >> 1;
    const int wn   = wid & 1;
    const size_t m0 = (size_t)blockIdx.z * SS + (size_t)s_base + (size_t)blockIdx.y * 128;
    const size_t n0 = (size_t)blockIdx.x * 128;

    // cp.async source pointers: per thread, A rows {ar, ar+64} chunk ac; B k-rows {br, br+16} chunk bc
    const int ar = t >> 2, ac = t & 3;
    const int br = t >> 4, bc = t & 15;
    const __nv_bfloat16* pAh = Ahi + (m0 + ar) * DD + ac * 8;
    const __nv_bfloat16* pAl = Alo + (m0 + ar) * DD + ac * 8;
    const __nv_bfloat16* pBh = Bhi + (size_t)br * DD + n0 + bc * 8;
    const __nv_bfloat16* pBl = Blo + (size_t)br * DD + n0 + bc * 8;
    const uint32_t sA0 = AHI + aoff(ar, ac);
    const uint32_t sA1 = AHI + aoff(ar + 64, ac);
    const uint32_t sB0 = BHI + boff(br, bc);
    const uint32_t sB1 = BHI + boff(br + 16, bc);

    // ldmatrix relative offsets (within stage)
    const int arow = wm * 32 + (lane & 7) + ((lane >> 3) & 1) * 8;
    const int akh  = (lane >> 4) & 1;
    uint32_t aAo[2][2];
    #pragma unroll
    for (int mt = 0; mt < 2; mt++)
        #pragma unroll
        for (int ks = 0; ks < 2; ks++)
            aAo[mt][ks] = AHI + aoff(arow + mt * 16, ks * 2 + akh);
    const int bpair = lane >> 4;
    const int bkr0  = ((lane >> 3) & 1) * 8 + (lane & 7);
    uint32_t aBo[2][4];
    #pragma unroll
    for (int ks = 0; ks < 2; ks++)
        #pragma unroll
        for (int bq = 0; bq < 4; bq++)
            aBo[ks][bq] = BHI + boff(ks * 16 + bkr0, wn * 8 + bq * 2 + bpair);

    float acc[2][8][4];
    #pragma unroll
    for (int mt = 0; mt < 2; mt++)
        #pragma unroll
        for (int nt = 0; nt < 8; nt++)
            #pragma unroll
            for (int i = 0; i < 4; i++) acc[mt][nt][i] = 0.0f;

    auto load_stage = [&](int stg, int k0) {
        const uint32_t s = sb + (uint32_t)stg * STAGE;
        cp_async16(s + sA0, pAh + k0);
        cp_async16(s + sA1, pAh + (size_t)64 * DD + k0);
        cp_async16(s + sA0 + (ALO - AHI), pAl + k0);
        cp_async16(s + sA1 + (ALO - AHI), pAl + (size_t)64 * DD + k0);
        cp_async16(s + sB0, pBh + (size_t)k0 * DD);
        cp_async16(s + sB1, pBh + (size_t)(k0 + 16) * DD);
        cp_async16(s + sB0 + (BLO - BHI), pBl + (size_t)k0 * DD);
        cp_async16(s + sB1 + (BLO - BHI), pBl + (size_t)(k0 + 16) * DD);
    };

    // prologue: tiles 0,1 into stages 0,1
    load_stage(0, 0);
    asm volatile("cp.async.commit_group;" ::: "memory");
    load_stage(1, 32);
    asm volatile("cp.async.commit_group;" ::: "memory");

    for (int tile = 0; tile < 64; tile++) {
        if (tile + 2 < 64) load_stage((tile + 2) % 3, (tile + 2) * 32);
        asm volatile("cp.async.commit_group;" ::: "memory");   // empty groups keep counting exact
        asm volatile("cp.async.wait_group 2;" ::: "memory");
        __syncthreads();

        const uint32_t stg = sb + (uint32_t)(tile % 3) * STAGE;
        #pragma unroll
        for (int ks = 0; ks < 2; ks++) {
            uint32_t ah[2][4], al[2][4], bx[4][4];
            ldsm4(ah[0], stg + aAo[0][ks]);
            ldsm4(ah[1], stg + aAo[1][ks]);
            ldsm4(al[0], stg + aAo[0][ks] + (ALO - AHI));
            ldsm4(al[1], stg + aAo[1][ks] + (ALO - AHI));
            #pragma unroll
            for (int bq = 0; bq < 4; bq++) ldsm4t(bx[bq], stg + aBo[ks][bq]);

            #pragma unroll
            for (int mt = 0; mt < 2; mt++)
                #pragma unroll
                for (int nt = 0; nt < 8; nt++) {
                    const int bq = nt >> 1, of = (nt & 1) * 2;
                    mma_bf16(acc[mt][nt], ah[mt], bx[bq][of], bx[bq][of + 1]);
                }
            #pragma unroll
            for (int mt = 0; mt < 2; mt++)
                #pragma unroll
                for (int nt = 0; nt < 8; nt++) {
                    const int bq = nt >> 1, of = (nt & 1) * 2;
                    mma_bf16(acc[mt][nt], al[mt], bx[bq][of], bx[bq][of + 1]);
                }
            // reload bx <- B_lo (reuses registers)
            #pragma unroll
            for (int bq = 0; bq < 4; bq++) ldsm4t(bx[bq], stg + aBo[ks][bq] + (BLO - BHI));
            #pragma unroll
            for (int mt = 0; mt < 2; mt++)
                #pragma unroll
                for (int nt = 0; nt < 8; nt++) {
                    const int bq = nt >> 1, of = (nt & 1) * 2;
                    mma_bf16(acc[mt][nt], ah[mt], bx[bq][of], bx[bq][of + 1]);
                }
        }
        __syncthreads();
    }

    const int g  = lane >> 2;
    const int tc = lane & 3;
    #pragma unroll
    for (int mt = 0; mt < 2; mt++) {
        const size_t row0 = m0 + wm * 32 + mt * 16 + g;
        #pragma unroll
        for (int nt = 0; nt < 8; nt++) {
            const size_t col = n0 + wn * 64 + nt * 8 + tc * 2;
            float b0 = 0.0f, b1 = 0.0f;
            if (bias != nullptr) { b0 = bias[col]; b1 = bias[col + 1]; }
            float2 v0 = make_float2(acc[mt][nt][0] + b0, acc[mt][nt][1] + b1);
            float2 v1 = make_float2(acc[mt][nt][2] + b0, acc[mt][nt][3] + b1);
            *(float2*)(C + row0 * DD + col)       = v0;
            *(float2*)(C + (row0 + 8) * DD + col) = v1;
        }
    }
}

// ============================================================================
// Scan chunk: steps [s_base, s_base+s_len). 64 blocks, one per (b, n).
// Emits y directly as bf16 hi/lo (pre-split input for the output GEMM).
// ============================================================================
__global__ __launch_bounds__(128, 1)
void scan_kernel(const float* __restrict__ x, const float* __restrict__ sin,
                 const float* __restrict__ SW,
                 __nv_bfloat16* __restrict__ yhi, __nv_bfloat16* __restrict__ ylo,
                 float* __restrict__ sfin, int s_base, int s_len) {
    const int b = blockIdx.x >> 4;
    const int n = blockIdx.x & 15;
    const int k = threadIdx.x;

    const float* Wn = SW + (size_t)n * HH * HH;
    ull w2[64];
    #pragma unroll
    for (int j = 0; j < 64; j++)
        w2[j] = pack2(Wn[(2 * j) * HH + k], Wn[(2 * j + 1) * HH + k]);

    __shared__ __align__(16) float sbuf[2][HH];
    sbuf[0][k] = sin[((size_t)b * NH + n) * HH + k];
    __syncthreads();

    const float* xp = x + ((size_t)b * SS + s_base) * DD + n * HH + k;
    __nv_bfloat16* yhp = yhi + ((size_t)b * SS + s_base) * DD + n * HH + k;
    __nv_bfloat16* ylp = ylo + ((size_t)b * SS + s_base) * DD + n * HH + k;

    float xa = xp[0];
    float xb = xp[DD];
    float xc = xp[2 * (size_t)DD];
    float v = 0.0f;

    for (int t = 0; t < s_len; t++) {
        float xn = 0.0f;
        if (t + 3 < s_len) xn = xp[(size_t)(t + 3) * DD];

        const ulonglong2* s4 = (const ulonglong2*)sbuf[t & 1];
        ull a0 = 0ull, a1 = 0ull, a2 = 0ull, a3 = 0ull;
        ull a4 = 0ull, a5 = 0ull, a6 = 0ull, a7 = 0ull;
        #pragma unroll
        for (int j = 0; j < 8; j++) {
            ulonglong2 p = s4[4 * j];
            ulonglong2 q = s4[4 * j + 1];
            ulonglong2 r = s4[4 * j + 2];
            ulonglong2 s = s4[4 * j + 3];
            a0 = ffma2(p.x, w2[8 * j + 0], a0);
            a1 = ffma2(p.y, w2[8 * j + 1], a1);
            a2 = ffma2(q.x, w2[8 * j + 2], a2);
            a3 = ffma2(q.y, w2[8 * j + 3], a3);
            a4 = ffma2(r.x, w2[8 * j + 4], a4);
            a5 = ffma2(r.y, w2[8 * j + 5], a5);
            a6 = ffma2(s.x, w2[8 * j + 6], a6);
            a7 = ffma2(s.y, w2[8 * j + 7], a7);
        }
        ull s01 = addf2(a0, a1), s23 = addf2(a2, a3);
        ull s45 = addf2(a4, a5), s67 = addf2(a6, a7);
        ull sall = addf2(addf2(s01, s23), addf2(s45, s67));
        float lo, hi;
        unpack2(sall, lo, hi);
        float dot = lo + hi;

        v = fast_tanh(dot + xa);
        __nv_bfloat16 h = __float2bfloat16(v);
        yhp[(size_t)t * DD] = h;
        ylp[(size_t)t * DD] = __float2bfloat16(v - __bfloat162float(h));
        sbuf[(t + 1) & 1][k] = v;

        xa = xb; xb = xc; xc = xn;
        __syncthreads();
    }

    sfin[((size_t)b * NH + n) * HH + k] = v;
}

// ============================================================================
// Launch: prelude conversions (overlapped) + 3-stream chunked pipeline.
// ============================================================================
extern "C" void kernel_launch(void* const* d_in, const int* in_sizes, int n_in,
                              void* d_out, int out_size) {
    const float* input  = (const float*)d_in[0];
    const float* state0 = (const float*)d_in[1];
    const float* w_in   = (const float*)d_in[2];
    const float* b_in   = (const float*)d_in[3];
    const float* sw     = (const float*)d_in[4];
    const float* w_out  = (const float*)d_in[5];
    float* out = (float*)d_out;

    float *xbuf, *stbuf;
    __nv_bfloat16 *inhi, *inlo, *yhi, *ylo, *wihi, *wilo, *wohi, *wolo;
    cudaGetSymbolAddress((void**)&xbuf, g_x);
    cudaGetSymbolAddress((void**)&stbuf, g_state);
    cudaGetSymbolAddress((void**)&inhi, g_inhi);
    cudaGetSymbolAddress((void**)&inlo, g_inlo);
    cudaGetSymbolAddress((void**)&yhi, g_yhi);
    cudaGetSymbolAddress((void**)&ylo, g_ylo);
    cudaGetSymbolAddress((void**)&wihi, g_wihi);
    cudaGetSymbolAddress((void**)&wilo, g_wilo);
    cudaGetSymbolAddress((void**)&wohi, g_wohi);
    cudaGetSymbolAddress((void**)&wolo, g_wolo);

    static cudaStream_t st1 = nullptr, st2 = nullptr;
    static cudaEvent_t ev_gin[NCH], ev_scan[NCH], ev_root, ev_w, ev_tail;
    if (st1 == nullptr) {
        int prio_lo, prio_hi;
        cudaDeviceGetStreamPriorityRange(&prio_lo, &prio_hi);
        cudaStreamCreateWithPriority(&st1, cudaStreamNonBlocking, prio_hi);  // scan: highest
        cudaStreamCreateWithFlags(&st2, cudaStreamNonBlocking);
        for (int c = 0; c < NCH; c++) {
            cudaEventCreateWithFlags(&ev_gin[c], cudaEventDisableTiming);
            cudaEventCreateWithFlags(&ev_scan[c], cudaEventDisableTiming);
        }
        cudaEventCreateWithFlags(&ev_root, cudaEventDisableTiming);
        cudaEventCreateWithFlags(&ev_w, cudaEventDisableTiming);
        cudaEventCreateWithFlags(&ev_tail, cudaEventDisableTiming);
    }

    const int smem_bytes = 3 * STAGE;  // 98304
    cudaFuncSetAttribute(gemm_mma_kernel, cudaFuncAttributeMaxDynamicSharedMemorySize, smem_bytes);

    // ---- prelude: weight splits on st2, input split on origin (overlapped) ----
    cudaEventRecord(ev_root, 0);
    cudaStreamWaitEvent(st2, ev_root, 0);
    cvt_split_kernel<<<4096, 256, 0, st2>>>(w_in, wihi, wilo, DD * DD / 4);
    cvt_split_kernel<<<4096, 256, 0, st2>>>(w_out, wohi, wolo, DD * DD / 4);
    cudaEventRecord(ev_w, st2);
    cvt_split_kernel<<<32768, 256>>>(input, inhi, inlo, MTOT * DD / 4);
    cudaStreamWaitEvent(0, ev_w, 0);

    dim3 ggrid(DD / 128, CH / 128, BB);  // (16, 4, 4) per chunk

    // Input-projection chunks on origin stream
    for (int c = 0; c < NCH; c++) {
        gemm_mma_kernel<<<ggrid, 256, smem_bytes>>>(inhi, inlo, wihi, wilo, b_in, xbuf, c * CH);
        cudaEventRecord(ev_gin[c], 0);
    }

    // Scan chunks on high-priority stream (sequential by state dependency)
    for (int c = 0; c < NCH; c++) {
        cudaStreamWaitEvent(st1, ev_gin[c], 0);
        const float* s_init = (c == 0) ? state0 : stbuf;
        scan_kernel<<<BB * NH, HH, 0, st1>>>(xbuf, s_init, sw, yhi, ylo, stbuf, c * CH, CH);
        cudaEventRecord(ev_scan[c], st1);
    }

    // Output-projection chunks on st2
    for (int c = 0; c < NCH; c++) {
        cudaStreamWaitEvent(st2, ev_scan[c], 0);
        gemm_mma_kernel<<<ggrid, 256, smem_bytes, st2>>>(yhi, ylo, wohi, wolo, nullptr, out, c * CH);
    }

    // Join forked work back to origin stream for graph capture
    cudaEventRecord(ev_tail, st2);
    cudaStreamWaitEvent(0, ev_tail, 0);
}